// round 5
// baseline (speedup 1.0000x reference)
#include <cuda_runtime.h>
#include <math.h>

// ---------------- problem constants ----------------
#define BB     16
#define F1N    16
#define CC     64
#define TTOT   1000
#define KK     64
#define C2N    32
#define PWN    16
#define EPSF   1e-5f

// ---------------- kernel-1 tiling ----------------
#define TILE   40          // time points per block
#define NTILE  25          // 25*40 = 1000
#define TSUB   20          // chunk of t per phase round
#define NCHUNK 2
#define TGRP   10          // t per thread in conv inner loop
#define XS_W   103         // TILE + 63 halo (odd -> conflict-free)
#define ES_S   22          // padded row stride for es (even -> 8B pairs)

// smem float counts (all even -> 8B alignment of every section)
#define NF_XS   (CC*XS_W + 1)     // 6593 -> +1 pad = 6594? keep even: 6594
#define NF_XSP  6594
#define NF_WSD  (F1N*KK*2)        // 2048 (dup pairs)
#define NF_AHD  (CC*CC*2)         // 8192 (dup pairs)
#define NF_DWD  (C2N*CC*2)        // 4096 (dup pairs)
#define NF_ES   (F1N*CC*ES_S)     // 22528
#define NF_XG   (CC*TSUB)         // 1280
#define NF_AX   (CC*TSUB)         // 1280
#define NF_SMALL 160
#define SMEM_FLOATS (NF_XSP+NF_WSD+NF_AHD+NF_DWD+NF_ES+NF_XG+NF_AX+NF_SMALL)
#define SMEM_BYTES  (SMEM_FLOATS*4)

// K2 tiling
#define K2B_W    8            // pool windows per k2b tile
#define K2B_T    (K2B_W*PWN)  // 128 t per tile
#define NTILE2   8            // 7 full + 1 partial (6 windows)
#define NPOOL    62           // 992/16

__device__ float g_h2[BB * C2N * TTOT];        // stage-3 output (2 MB)
__device__ float g_psum[BB * C2N * NTILE];     // per-tile sum partials
__device__ float g_pmax[BB * C2N * NTILE];     // per-tile max partials
__device__ float g_q[BB * C2N * NPOOL];        // pooled pre-sepconv

typedef unsigned long long ull;

__device__ __forceinline__ float eluf(float v) { return v > 0.f ? v : expm1f(v); }
__device__ __forceinline__ float sigmf(float z) { return 1.f / (1.f + expf(-z)); }

__device__ __forceinline__ ull fma2(ull a, ull b, ull c) {
    ull d;
    asm("fma.rn.f32x2 %0, %1, %2, %3;" : "=l"(d) : "l"(a), "l"(b), "l"(c));
    return d;
}
__device__ __forceinline__ ull pack2(float lo, float hi) {
    ull d;
    asm("mov.b64 %0, {%1, %2};" : "=l"(d) : "f"(lo), "f"(hi));
    return d;
}
__device__ __forceinline__ void unpack2(ull v, float& lo, float& hi) {
    asm("mov.b64 {%0, %1}, %2;" : "=f"(lo), "=f"(hi) : "l"(v));
}

// ============================================================
// Kernel 1: temporal conv (f32x2) + BN1 + ELU + GCN residual +
//           depthwise expansion + BN2 -> g_h2 (+ per-tile stats)
// grid (NTILE, BB), 512 threads
// ============================================================
__global__ void __launch_bounds__(512, 1)
k1_front(const float* __restrict__ x,
         const float* __restrict__ ahat_g,
         const float* __restrict__ w1,  const float* __restrict__ b1c,
         const float* __restrict__ g1,  const float* __restrict__ bb1,
         const float* __restrict__ m1,  const float* __restrict__ v1,
         const float* __restrict__ gcw, const float* __restrict__ gcb,
         const float* __restrict__ dww_g, const float* __restrict__ dwb,
         const float* __restrict__ g2,  const float* __restrict__ bb2,
         const float* __restrict__ m2,  const float* __restrict__ v2)
{
    extern __shared__ float sm[];
    float* xs  = sm;                 // [CC][XS_W]
    float* wsd = xs  + NF_XSP;       // [F1][KK] dup pairs
    float* ahd = wsd + NF_WSD;       // [CC][CC] dup pairs
    float* dwd = ahd + NF_AHD;       // [C2][CC] dup pairs
    float* es  = dwd + NF_DWD;       // [F1][CC][ES_S]
    float* xg  = es  + NF_ES;        // [CC][TSUB] (reused for stats stash)
    float* ax  = xg  + NF_XG;        // [CC][TSUB]
    float* o1s = ax  + NF_AX;        // [F1]
    float* gw  = o1s + F1N;          // [F1]
    float* s2  = gw  + F1N;          // [C2]
    float* sh2 = s2  + C2N;          // [C2]
    float* cst = sh2 + C2N;          // [C2]

    const int tid = threadIdx.x;
    const int b   = blockIdx.y;
    const int t0  = blockIdx.x * TILE;

    // ---- cooperative loads ----
    for (int i = tid; i < CC * XS_W; i += 512) {
        int c = i / XS_W, j = i % XS_W;
        int tg = t0 - 31 + j;
        xs[i] = (tg >= 0 && tg < TTOT) ? x[(b * CC + c) * TTOT + tg] : 0.f;
    }
    for (int i = tid; i < F1N * KK; i += 512) {
        int f = i / KK;
        float s1 = g1[f] * rsqrtf(v1[f] + EPSF);
        float w = w1[i] * s1;
        wsd[2 * i] = w; wsd[2 * i + 1] = w;
    }
    for (int i = tid; i < CC * CC; i += 512) {
        float v = ahat_g[i];
        ahd[2 * i] = v; ahd[2 * i + 1] = v;
    }
    for (int i = tid; i < C2N * CC; i += 512) {
        float v = dww_g[i];
        dwd[2 * i] = v; dwd[2 * i + 1] = v;
    }
    if (tid < F1N) {
        float s1 = g1[tid] * rsqrtf(v1[tid] + EPSF);
        o1s[tid] = b1c[tid] * s1 + bb1[tid] - m1[tid] * s1;
        gw[tid]  = gcw[tid];
    }
    if (tid < C2N) {
        float s = g2[tid] * rsqrtf(v2[tid] + EPSF);
        s2[tid]  = s;
        sh2[tid] = bb2[tid] - m2[tid] * s;
    }
    __syncthreads();
    if (tid < C2N) {
        float wsum = 0.f;
        for (int c = 0; c < CC; ++c) wsum += dwd[2 * (tid * CC + c)];
        cst[tid] = gcb[tid >> 1] * wsum + dwb[tid];
    }
    __syncthreads();

    // thread -> (fq, tg, c)
    const int fq = tid >> 7;         // 0..3
    const int tg = (tid >> 6) & 1;   // 0..1
    const int c  = tid & 63;
    const float* xrow = xs + c * XS_W;
    const ull* wd0 = (const ull*)wsd + (fq * 4 + 0) * KK;
    const ull* wd1 = (const ull*)wsd + (fq * 4 + 1) * KK;
    const ull* wd2 = (const ull*)wsd + (fq * 4 + 2) * KK;
    const ull* wd3 = (const ull*)wsd + (fq * 4 + 3) * KK;

    float stat_s = 0.f, stat_m = -INFINITY;

    for (int chk = 0; chk < NCHUNK; ++chk) {
        const int ct = chk * TSUB;

        // ---- phase A: conv (f32x2) + BN1 + ELU -> es ----
        {
            const int base = ct + tg * TGRP;
            ull a0[5], a1[5], a2[5], a3[5], P[10];
            #pragma unroll
            for (int m = 0; m < 5; ++m) a0[m] = a1[m] = a2[m] = a3[m] = 0ull;
            float xprev = xrow[base];
            #pragma unroll
            for (int p = 0; p < 10; ++p) {
                float xn = xrow[base + p + 1];
                P[p] = pack2(xprev, xn);
                xprev = xn;
            }
            // invariant at tap j: P holds pairs (x[j+p'],x[j+p'+1]) for p'=0..9,
            // indexed P[(j+p')%10]; xprev = x[base+j+10]
            #pragma unroll
            for (int j = 0; j < KK; ++j) {
                ull w0 = wd0[j], w1v = wd1[j], w2v = wd2[j], w3v = wd3[j];
                #pragma unroll
                for (int m = 0; m < 5; ++m) {
                    ull xv = P[(j + 2 * m) % 10];
                    a0[m] = fma2(w0, xv, a0[m]);
                    a1[m] = fma2(w1v, xv, a1[m]);
                    a2[m] = fma2(w2v, xv, a2[m]);
                    a3[m] = fma2(w3v, xv, a3[m]);
                }
                if (j < 62) {
                    float xn = xrow[base + j + 11];
                    P[j % 10] = pack2(xprev, xn);
                    xprev = xn;
                }
            }
            const int f0 = fq * 4;
            const int eoff = tg * (TGRP / 2);   // in ull units
            ull* e0 = (ull*)es + ((f0 + 0) * CC + c) * (ES_S / 2) + eoff;
            ull* e1 = (ull*)es + ((f0 + 1) * CC + c) * (ES_S / 2) + eoff;
            ull* e2 = (ull*)es + ((f0 + 2) * CC + c) * (ES_S / 2) + eoff;
            ull* e3 = (ull*)es + ((f0 + 3) * CC + c) * (ES_S / 2) + eoff;
            float o0 = o1s[f0], o1 = o1s[f0 + 1], o2 = o1s[f0 + 2], o3 = o1s[f0 + 3];
            #pragma unroll
            for (int m = 0; m < 5; ++m) {
                float lo, hi;
                unpack2(a0[m], lo, hi);
                e0[m] = pack2(eluf(lo + o0), eluf(hi + o0));
                unpack2(a1[m], lo, hi);
                e1[m] = pack2(eluf(lo + o1), eluf(hi + o1));
                unpack2(a2[m], lo, hi);
                e2[m] = pack2(eluf(lo + o2), eluf(hi + o2));
                unpack2(a3[m], lo, hi);
                e3[m] = pack2(eluf(lo + o3), eluf(hi + o3));
            }
        }
        __syncthreads();

        // ---- phase B: xg = mean_f es (scalar) ----
        for (int idx = tid; idx < CC * TSUB; idx += 512) {
            int cc = idx / TSUB, tt = idx % TSUB;
            float s = 0.f;
            #pragma unroll
            for (int f = 0; f < F1N; ++f) s += es[(f * CC + cc) * ES_S + tt];
            xg[idx] = s * (1.f / F1N);
        }
        __syncthreads();

        // ---- phase C: ax = a_hat @ xg (f32x2 pairs) ----
        for (int idx = tid; idx < CC * (TSUB / 2); idx += 512) {
            int cc = idx / (TSUB / 2), tp = idx % (TSUB / 2);
            const ull* ar  = (const ull*)ahd + cc * CC;
            const ull* xgp = (const ull*)xg;
            ull acc = 0ull;
            #pragma unroll 8
            for (int j = 0; j < CC; ++j)
                acc = fma2(ar[j], xgp[j * (TSUB / 2) + tp], acc);
            ((ull*)ax)[cc * (TSUB / 2) + tp] = acc;
        }
        __syncthreads();

        // ---- phase D: depthwise expansion + GCN + BN2 -> g_h2 ----
        for (int idx = tid; idx < C2N * (TSUB / 2); idx += 512) {
            int c2 = idx / (TSUB / 2), tp = idx % (TSUB / 2);
            int f = c2 >> 1;
            ull gw2 = pack2(gw[f], gw[f]);
            const ull* dr  = (const ull*)dwd + c2 * CC;
            const ull* axp = (const ull*)ax;
            const ull* esp = (const ull*)es;
            ull acc = 0ull;
            #pragma unroll 8
            for (int cc = 0; cc < CC; ++cc) {
                ull t = fma2(gw2, axp[cc * (TSUB / 2) + tp],
                             esp[(f * CC + cc) * (ES_S / 2) + tp]);
                acc = fma2(dr[cc], t, acc);
            }
            float lo, hi;
            unpack2(acc, lo, hi);
            float sv = s2[c2], sh = sh2[c2], cs = cst[c2];
            float2 outv = make_float2((lo + cs) * sv + sh, (hi + cs) * sv + sh);
            *(float2*)&g_h2[(b * C2N + c2) * TTOT + t0 + ct + 2 * tp] = outv;
            ((ull*)xg)[c2 * (TSUB / 2) + tp] = pack2(outv.x, outv.y);
        }
        __syncthreads();

        // ---- stats accumulate (threads 0..31, one c2 each) ----
        if (tid < C2N) {
            #pragma unroll
            for (int tt = 0; tt < TSUB; ++tt) {
                float v = xg[tid * TSUB + tt];
                stat_s += v; stat_m = fmaxf(stat_m, v);
            }
        }
        __syncthreads();
    }

    if (tid < C2N) {
        g_psum[(b * C2N + tid) * NTILE + blockIdx.x] = stat_s;
        g_pmax[(b * C2N + tid) * NTILE + blockIdx.x] = stat_m;
    }
}

// ============================================================
// Kernel 2b: channel attn + spatial attn + ELU + pool16 -> g_q
// grid (NTILE2, BB), 256 threads
// ============================================================
#define H2S_S 131
__global__ void __launch_bounds__(256, 4)
k2b_attpool(const float* __restrict__ caw1, const float* __restrict__ cab1,
            const float* __restrict__ caw2, const float* __restrict__ cab2,
            const float* __restrict__ saw,
            const float* __restrict__ sag, const float* __restrict__ sab,
            const float* __restrict__ sam, const float* __restrict__ sav)
{
    __shared__ float att[C2N];
    __shared__ float h2s[C2N * H2S_S];
    __shared__ float mms[K2B_T + 2], mxs[K2B_T + 2], sgs[K2B_T];
    __shared__ float sstat[C2N];

    const int tile = blockIdx.x, b = blockIdx.y;
    const int tid  = threadIdx.x;
    const int t0   = tile * K2B_T;
    const int tw   = (tile == NTILE2 - 1) ? (NPOOL * PWN - t0) : K2B_T;
    const int nw   = tw / PWN;

    if (tid < C2N) {
        float s = 0.f, m = -INFINITY;
        const float* ps = g_psum + (b * C2N + tid) * NTILE;
        const float* pm = g_pmax + (b * C2N + tid) * NTILE;
        #pragma unroll 5
        for (int tl = 0; tl < NTILE; ++tl) {
            s += ps[tl]; m = fmaxf(m, pm[tl]);
        }
        sstat[tid] = s * (1.f / TTOT) + m;
    }
    __syncthreads();
    if (tid < C2N) {
        float r0 = cab1[0], r1 = cab1[1];
        for (int j = 0; j < C2N; ++j) {
            r0 += caw1[j] * sstat[j];
            r1 += caw1[C2N + j] * sstat[j];
        }
        r0 = fmaxf(r0, 0.f); r1 = fmaxf(r1, 0.f);
        att[tid] = sigmf(cab2[tid] + caw2[tid * 2] * r0 + caw2[tid * 2 + 1] * r1);
    }
    __syncthreads();

    const float* h2 = g_h2 + b * C2N * TTOT;
    for (int idx = tid; idx < C2N * (tw + 2); idx += 256) {
        int c2 = idx / (tw + 2), j = idx % (tw + 2);
        int t = t0 - 1 + j;
        float v = (t >= 0 && t < TTOT) ? h2[c2 * TTOT + t] * att[c2] : 0.f;
        h2s[c2 * H2S_S + j] = v;
    }
    __syncthreads();

    for (int j = tid; j < tw + 2; j += 256) {
        float s = 0.f, mx = -INFINITY;
        #pragma unroll 8
        for (int c2 = 0; c2 < C2N; ++c2) {
            float v = h2s[c2 * H2S_S + j];
            s += v; mx = fmaxf(mx, v);
        }
        mms[j] = s * (1.f / C2N);
        mxs[j] = mx;
    }
    __syncthreads();

    {
        float ssa = sag[0] * rsqrtf(sav[0] + EPSF);
        float sha = sab[0] - sam[0] * ssa;
        for (int j = tid; j < tw; j += 256) {
            int t = t0 + j;
            float acc = 0.f;
            #pragma unroll
            for (int kw = 0; kw < 3; ++kw) {
                int tt = t - 1 + kw;
                if (tt >= 0 && tt < TTOT)
                    acc += saw[3 + kw] * mms[j + kw] + saw[12 + kw] * mxs[j + kw];
            }
            sgs[j] = sigmf(acc * ssa + sha);
        }
    }
    __syncthreads();

    {
        int c2 = tid & 31, w = tid >> 5;
        if (w < nw) {
            float acc = 0.f;
            #pragma unroll
            for (int j = 0; j < PWN; ++j) {
                int tl = w * PWN + j;
                acc += eluf(h2s[c2 * H2S_S + tl + 1] * sgs[tl]);
            }
            g_q[(b * C2N + c2) * NPOOL + tile * K2B_W + w] = acc * (1.f / PWN);
        }
    }
}

// ============================================================
// Kernel 2c: depthwise sep conv + BN3 + ELU + pool16 -> out
// grid (BB), 256 threads — lane-group-of-16 parallel reduction
// ============================================================
__global__ void __launch_bounds__(256, 4)
k2c_tail(const float* __restrict__ sepw, const float* __restrict__ sepb,
         const float* __restrict__ g3, const float* __restrict__ bb3,
         const float* __restrict__ m3, const float* __restrict__ v3,
         float* __restrict__ out)
{
    __shared__ float qs[C2N * NPOOL];
    __shared__ float sw[C2N * PWN];
    const int b = blockIdx.x, tid = threadIdx.x;
    for (int i = tid; i < C2N * NPOOL; i += 256)
        qs[i] = g_q[b * C2N * NPOOL + i];
    for (int i = tid; i < C2N * PWN; i += 256)
        sw[i] = sepw[i];
    __syncthreads();

    const int j  = tid & 15;
    const int e0 = tid >> 4;
    for (int r = 0; r < 6; ++r) {
        int e  = e0 + r * 16;          // 0..95 = c2*3 + to
        int c2 = e / 3, to = e % 3;
        int t  = to * PWN + j;
        float y = sepb[c2];
        #pragma unroll
        for (int u = 0; u < PWN; ++u) {
            int tq = t - 7 + u;
            if (tq >= 0 && tq < NPOOL) y = fmaf(sw[c2 * PWN + u], qs[c2 * NPOOL + tq], y);
        }
        float s3  = g3[c2] * rsqrtf(v3[c2] + EPSF);
        float sh3 = bb3[c2] - m3[c2] * s3;
        float v = eluf(y * s3 + sh3);
        #pragma unroll
        for (int o = 8; o > 0; o >>= 1)
            v += __shfl_down_sync(0xffffffffu, v, o, 16);
        if (j == 0) out[b * (C2N * 3) + e] = v * (1.f / PWN);
    }
}

// ============================================================
extern "C" void kernel_launch(void* const* d_in, const int* in_sizes, int n_in,
                              void* d_out, int out_size)
{
    const float* x     = (const float*)d_in[0];
    const float* ahat  = (const float*)d_in[1];
    const float* w1    = (const float*)d_in[2];
    const float* b1c   = (const float*)d_in[3];
    const float* g1    = (const float*)d_in[4];
    const float* bb1   = (const float*)d_in[5];
    const float* m1    = (const float*)d_in[6];
    const float* v1    = (const float*)d_in[7];
    const float* gcw   = (const float*)d_in[8];
    const float* gcb   = (const float*)d_in[9];
    const float* dww   = (const float*)d_in[10];
    const float* dwb   = (const float*)d_in[11];
    const float* g2    = (const float*)d_in[12];
    const float* bb2   = (const float*)d_in[13];
    const float* m2    = (const float*)d_in[14];
    const float* v2    = (const float*)d_in[15];
    const float* caw1  = (const float*)d_in[16];
    const float* cab1  = (const float*)d_in[17];
    const float* caw2  = (const float*)d_in[18];
    const float* cab2  = (const float*)d_in[19];
    const float* saw   = (const float*)d_in[20];
    const float* sag   = (const float*)d_in[21];
    const float* sab   = (const float*)d_in[22];
    const float* sam   = (const float*)d_in[23];
    const float* sav   = (const float*)d_in[24];
    const float* sepw  = (const float*)d_in[25];
    const float* sepb  = (const float*)d_in[26];
    const float* g3    = (const float*)d_in[27];
    const float* bb3   = (const float*)d_in[28];
    const float* m3    = (const float*)d_in[29];
    const float* v3    = (const float*)d_in[30];

    cudaFuncSetAttribute(k1_front, cudaFuncAttributeMaxDynamicSharedMemorySize,
                         SMEM_BYTES);

    dim3 grid1(NTILE, BB);
    k1_front<<<grid1, 512, SMEM_BYTES>>>(x, ahat, w1, b1c, g1, bb1, m1, v1,
                                         gcw, gcb, dww, dwb, g2, bb2, m2, v2);

    dim3 grid2b(NTILE2, BB);
    k2b_attpool<<<grid2b, 256>>>(caw1, cab1, caw2, cab2, saw, sag, sab, sam, sav);

    k2c_tail<<<BB, 256>>>(sepw, sepb, g3, bb3, m3, v3, (float*)d_out);
}

// round 6
// speedup vs baseline: 1.4355x; 1.4355x over previous
#include <cuda_runtime.h>
#include <math.h>

// ---------------- problem constants ----------------
#define BB     16
#define F1N    16
#define CC     64
#define TTOT   1000
#define KK     64
#define C2N    32
#define PWN    16
#define EPSF   1e-5f

// ---------------- kernel-1 tiling ----------------
#define TILE   112         // time points per block
#define NTILE  9           // 9*112 = 1008 >= 1000 (last tile partial)
#define TSUB   16          // chunk of t per phase round (power of 2)
#define NCHUNK 7           // 7*16 = 112
#define TGRP   8           // t per thread in conv inner loop
#define XS_W   177         // TILE + 63 halo + 2 (odd -> conflict-free)
#define ES_S   17          // padded row stride for es (odd)

// smem float counts
#define NF_XS   (CC*XS_W)       // 11328
#define NF_WS   (F1N*KK)        // 1024
#define NF_AH   (CC*CC)         // 4096
#define NF_DW   (C2N*CC)        // 2048
#define NF_ES   (F1N*CC*ES_S)   // 17408
#define NF_XG   (CC*TSUB)       // 1024 (reused as stats stash)
#define NF_AX   (CC*TSUB)       // 1024
#define NF_SMALL 144
#define SMEM_FLOATS (NF_XS+NF_WS+NF_AH+NF_DW+NF_ES+NF_XG+NF_AX+NF_SMALL)
#define SMEM_BYTES  (SMEM_FLOATS*4)   // ~152 KB

// K2 tiling
#define K2B_W    8            // pool windows per k2b tile
#define K2B_T    (K2B_W*PWN)  // 128 t per tile
#define NTILE2   8            // 7 full + 1 partial (6 windows)
#define NPOOL    62           // 992/16

__device__ float g_h2[BB * C2N * TTOT];        // stage-3 output (2 MB)
__device__ float g_psum[BB * C2N * NTILE];     // per-tile sum partials
__device__ float g_pmax[BB * C2N * NTILE];     // per-tile max partials
__device__ float g_q[BB * C2N * NPOOL];        // pooled pre-sepconv

__device__ __forceinline__ float eluf(float v) { return v > 0.f ? v : expm1f(v); }
__device__ __forceinline__ float sigmf(float z) { return 1.f / (1.f + expf(-z)); }

// ============================================================
// Kernel 1: temporal conv + BN1 + ELU + GCN residual +
//           depthwise expansion + BN2 -> g_h2 (+ per-tile stats)
// grid (NTILE, BB) = 144 blocks (single wave), 1024 threads
// ============================================================
__global__ void __launch_bounds__(1024, 1)
k1_front(const float* __restrict__ x,
         const float* __restrict__ ahat_g,
         const float* __restrict__ w1,  const float* __restrict__ b1c,
         const float* __restrict__ g1,  const float* __restrict__ bb1,
         const float* __restrict__ m1,  const float* __restrict__ v1,
         const float* __restrict__ gcw, const float* __restrict__ gcb,
         const float* __restrict__ dww_g, const float* __restrict__ dwb,
         const float* __restrict__ g2,  const float* __restrict__ bb2,
         const float* __restrict__ m2,  const float* __restrict__ v2)
{
    extern __shared__ float sm[];
    float* xs  = sm;                 // [CC][XS_W]
    float* ws  = xs  + NF_XS;        // [F1][KK] (BN1-scaled weights)
    float* ah  = ws  + NF_WS;        // [CC][CC]
    float* dw  = ah  + NF_AH;        // [C2][CC]
    float* es  = dw  + NF_DW;        // [F1][CC][ES_S]
    float* xg  = es  + NF_ES;        // [CC][TSUB] (reused as stats stash)
    float* ax  = xg  + NF_XG;        // [CC][TSUB]
    float* o1s = ax  + NF_AX;        // [F1]
    float* gw  = o1s + F1N;          // [F1]
    float* s2  = gw  + F1N;          // [C2]
    float* sh2 = s2  + C2N;          // [C2]
    float* cst = sh2 + C2N;          // [C2]

    const int tid = threadIdx.x;
    const int b   = blockIdx.y;
    const int t0  = blockIdx.x * TILE;

    // ---- cooperative loads ----
    for (int i = tid; i < NF_XS; i += 1024) {
        int c = i / XS_W, j = i % XS_W;
        int tg = t0 - 31 + j;
        xs[i] = (tg >= 0 && tg < TTOT) ? x[(b * CC + c) * TTOT + tg] : 0.f;
    }
    for (int i = tid; i < NF_WS; i += 1024) {
        int f = i / KK;
        float s1 = g1[f] * rsqrtf(v1[f] + EPSF);
        ws[i] = w1[i] * s1;
    }
    for (int i = tid; i < NF_AH; i += 1024) ah[i] = ahat_g[i];
    for (int i = tid; i < NF_DW; i += 1024) dw[i] = dww_g[i];
    if (tid < F1N) {
        float s1 = g1[tid] * rsqrtf(v1[tid] + EPSF);
        o1s[tid] = b1c[tid] * s1 + bb1[tid] - m1[tid] * s1;
        gw[tid]  = gcw[tid];
    }
    if (tid < C2N) {
        float s = g2[tid] * rsqrtf(v2[tid] + EPSF);
        s2[tid]  = s;
        sh2[tid] = bb2[tid] - m2[tid] * s;
    }
    __syncthreads();
    if (tid < C2N) {
        float wsum = 0.f;
        for (int c = 0; c < CC; ++c) wsum += dw[tid * CC + c];
        cst[tid] = gcb[tid >> 1] * wsum + dwb[tid];
    }
    __syncthreads();

    // thread -> (fp, tg, c): warp spans 32 consecutive c (conflict-free)
    const int fp = tid >> 7;          // 0..7 (filter pair)
    const int tg = (tid >> 6) & 1;    // 0..1 (t half)
    const int c  = tid & 63;
    const float* xrow = xs + c * XS_W;
    const float* wr0 = ws + (fp * 2 + 0) * KK;
    const float* wr1 = ws + (fp * 2 + 1) * KK;

    const int cc_idx = tid >> 4;      // for phases B/C (0..63)
    const int tt_idx = tid & 15;

    float stat_s = 0.f, stat_m = -INFINITY;

    for (int chk = 0; chk < NCHUNK; ++chk) {
        const int ct = chk * TSUB;

        // ---- phase A: conv + BN1 + ELU -> es ----
        {
            const int base = ct + tg * TGRP;
            float a0[TGRP], a1[TGRP], win[TGRP];
            #pragma unroll
            for (int i = 0; i < TGRP; ++i) {
                a0[i] = a1[i] = 0.f;
                win[i] = xrow[base + i];
            }
            int k = 0;
            #pragma unroll 2
            for (int m = 0; m < 8; ++m) {
                #pragma unroll
                for (int kk = 0; kk < 8; ++kk) {
                    float w0 = wr0[k + kk], w1v = wr1[k + kk];
                    #pragma unroll
                    for (int i = 0; i < TGRP; ++i) {
                        float xv = win[(kk + i) & 7];
                        a0[i] = fmaf(w0, xv, a0[i]);
                        a1[i] = fmaf(w1v, xv, a1[i]);
                    }
                    win[kk] = xrow[base + k + kk + TGRP];
                }
                k += 8;
            }
            const int f0 = fp * 2;
            float* e0 = es + ((f0 + 0) * CC + c) * ES_S + tg * TGRP;
            float* e1 = es + ((f0 + 1) * CC + c) * ES_S + tg * TGRP;
            float o0 = o1s[f0], o1 = o1s[f0 + 1];
            #pragma unroll
            for (int i = 0; i < TGRP; ++i) {
                e0[i] = eluf(a0[i] + o0);
                e1[i] = eluf(a1[i] + o1);
            }
        }
        __syncthreads();

        // ---- phase B: xg = mean_f es (1 item/thread) ----
        {
            float s = 0.f;
            #pragma unroll
            for (int f = 0; f < F1N; ++f)
                s += es[(f * CC + cc_idx) * ES_S + tt_idx];
            xg[cc_idx * TSUB + tt_idx] = s * (1.f / F1N);
        }
        __syncthreads();

        // ---- phase C: ax = a_hat @ xg (1 item/thread) ----
        {
            const float* ar = ah + cc_idx * CC;
            float s = 0.f;
            #pragma unroll 8
            for (int j = 0; j < CC; ++j)
                s = fmaf(ar[j], xg[j * TSUB + tt_idx], s);
            ax[cc_idx * TSUB + tt_idx] = s;
        }
        __syncthreads();

        // ---- phase D: depthwise expansion + GCN + BN2 -> g_h2 ----
        if (tid < C2N * TSUB) {
            int c2 = tid >> 4, tt = tid & 15;
            int f = c2 >> 1;
            float gwf = gw[f];
            const float* dr = dw + c2 * CC;
            float s = 0.f;
            #pragma unroll 8
            for (int cc = 0; cc < CC; ++cc)
                s = fmaf(dr[cc], es[(f * CC + cc) * ES_S + tt] + gwf * ax[cc * TSUB + tt], s);
            float outv = (s + cst[c2]) * s2[c2] + sh2[c2];
            int t = t0 + ct + tt;
            if (t < TTOT) g_h2[(b * C2N + c2) * TTOT + t] = outv;
            xg[c2 * TSUB + tt] = outv;      // stash (xg dead after phase C)
        }
        __syncthreads();

        // ---- stats accumulate (threads 0..31, one c2 each) ----
        if (tid < C2N) {
            #pragma unroll
            for (int tt = 0; tt < TSUB; ++tt) {
                if (t0 + ct + tt < TTOT) {
                    float v = xg[tid * TSUB + tt];
                    stat_s += v; stat_m = fmaxf(stat_m, v);
                }
            }
        }
        __syncthreads();
    }

    if (tid < C2N) {
        g_psum[(b * C2N + tid) * NTILE + blockIdx.x] = stat_s;
        g_pmax[(b * C2N + tid) * NTILE + blockIdx.x] = stat_m;
    }
}

// ============================================================
// Kernel 2b: channel attn + spatial attn + ELU + pool16 -> g_q
// grid (NTILE2, BB), 256 threads
// ============================================================
#define H2S_S 131
__global__ void __launch_bounds__(256, 4)
k2b_attpool(const float* __restrict__ caw1, const float* __restrict__ cab1,
            const float* __restrict__ caw2, const float* __restrict__ cab2,
            const float* __restrict__ saw,
            const float* __restrict__ sag, const float* __restrict__ sab,
            const float* __restrict__ sam, const float* __restrict__ sav)
{
    __shared__ float att[C2N];
    __shared__ float h2s[C2N * H2S_S];
    __shared__ float mms[K2B_T + 2], mxs[K2B_T + 2], sgs[K2B_T];
    __shared__ float sstat[C2N];

    const int tile = blockIdx.x, b = blockIdx.y;
    const int tid  = threadIdx.x;
    const int t0   = tile * K2B_T;
    const int tw   = (tile == NTILE2 - 1) ? (NPOOL * PWN - t0) : K2B_T;
    const int nw   = tw / PWN;

    if (tid < C2N) {
        float s = 0.f, m = -INFINITY;
        const float* ps = g_psum + (b * C2N + tid) * NTILE;
        const float* pm = g_pmax + (b * C2N + tid) * NTILE;
        #pragma unroll
        for (int tl = 0; tl < NTILE; ++tl) {
            s += ps[tl]; m = fmaxf(m, pm[tl]);
        }
        sstat[tid] = s * (1.f / TTOT) + m;
    }
    __syncthreads();
    if (tid < C2N) {
        float r0 = cab1[0], r1 = cab1[1];
        for (int j = 0; j < C2N; ++j) {
            r0 += caw1[j] * sstat[j];
            r1 += caw1[C2N + j] * sstat[j];
        }
        r0 = fmaxf(r0, 0.f); r1 = fmaxf(r1, 0.f);
        att[tid] = sigmf(cab2[tid] + caw2[tid * 2] * r0 + caw2[tid * 2 + 1] * r1);
    }
    __syncthreads();

    const float* h2 = g_h2 + b * C2N * TTOT;
    for (int idx = tid; idx < C2N * (tw + 2); idx += 256) {
        int c2 = idx / (tw + 2), j = idx % (tw + 2);
        int t = t0 - 1 + j;
        float v = (t >= 0 && t < TTOT) ? h2[c2 * TTOT + t] * att[c2] : 0.f;
        h2s[c2 * H2S_S + j] = v;
    }
    __syncthreads();

    for (int j = tid; j < tw + 2; j += 256) {
        float s = 0.f, mx = -INFINITY;
        #pragma unroll 8
        for (int c2 = 0; c2 < C2N; ++c2) {
            float v = h2s[c2 * H2S_S + j];
            s += v; mx = fmaxf(mx, v);
        }
        mms[j] = s * (1.f / C2N);
        mxs[j] = mx;
    }
    __syncthreads();

    {
        float ssa = sag[0] * rsqrtf(sav[0] + EPSF);
        float sha = sab[0] - sam[0] * ssa;
        for (int j = tid; j < tw; j += 256) {
            int t = t0 + j;
            float acc = 0.f;
            #pragma unroll
            for (int kw = 0; kw < 3; ++kw) {
                int tt = t - 1 + kw;
                if (tt >= 0 && tt < TTOT)
                    acc += saw[3 + kw] * mms[j + kw] + saw[12 + kw] * mxs[j + kw];
            }
            sgs[j] = sigmf(acc * ssa + sha);
        }
    }
    __syncthreads();

    {
        int c2 = tid & 31, w = tid >> 5;
        if (w < nw) {
            float acc = 0.f;
            #pragma unroll
            for (int j = 0; j < PWN; ++j) {
                int tl = w * PWN + j;
                acc += eluf(h2s[c2 * H2S_S + tl + 1] * sgs[tl]);
            }
            g_q[(b * C2N + c2) * NPOOL + tile * K2B_W + w] = acc * (1.f / PWN);
        }
    }
}

// ============================================================
// Kernel 2c: depthwise sep conv + BN3 + ELU + pool16 -> out
// grid (BB), 256 threads — lane-group-of-16 parallel reduction
// ============================================================
__global__ void __launch_bounds__(256, 4)
k2c_tail(const float* __restrict__ sepw, const float* __restrict__ sepb,
         const float* __restrict__ g3, const float* __restrict__ bb3,
         const float* __restrict__ m3, const float* __restrict__ v3,
         float* __restrict__ out)
{
    __shared__ float qs[C2N * NPOOL];
    __shared__ float sw[C2N * PWN];
    const int b = blockIdx.x, tid = threadIdx.x;
    for (int i = tid; i < C2N * NPOOL; i += 256)
        qs[i] = g_q[b * C2N * NPOOL + i];
    for (int i = tid; i < C2N * PWN; i += 256)
        sw[i] = sepw[i];
    __syncthreads();

    const int j  = tid & 15;
    const int e0 = tid >> 4;
    for (int r = 0; r < 6; ++r) {
        int e  = e0 + r * 16;          // 0..95 = c2*3 + to
        int c2 = e / 3, to = e % 3;
        int t  = to * PWN + j;
        float y = sepb[c2];
        #pragma unroll
        for (int u = 0; u < PWN; ++u) {
            int tq = t - 7 + u;
            if (tq >= 0 && tq < NPOOL) y = fmaf(sw[c2 * PWN + u], qs[c2 * NPOOL + tq], y);
        }
        float s3  = g3[c2] * rsqrtf(v3[c2] + EPSF);
        float sh3 = bb3[c2] - m3[c2] * s3;
        float v = eluf(y * s3 + sh3);
        #pragma unroll
        for (int o = 8; o > 0; o >>= 1)
            v += __shfl_down_sync(0xffffffffu, v, o, 16);
        if (j == 0) out[b * (C2N * 3) + e] = v * (1.f / PWN);
    }
}

// ============================================================
extern "C" void kernel_launch(void* const* d_in, const int* in_sizes, int n_in,
                              void* d_out, int out_size)
{
    const float* x     = (const float*)d_in[0];
    const float* ahat  = (const float*)d_in[1];
    const float* w1    = (const float*)d_in[2];
    const float* b1c   = (const float*)d_in[3];
    const float* g1    = (const float*)d_in[4];
    const float* bb1   = (const float*)d_in[5];
    const float* m1    = (const float*)d_in[6];
    const float* v1    = (const float*)d_in[7];
    const float* gcw   = (const float*)d_in[8];
    const float* gcb   = (const float*)d_in[9];
    const float* dww   = (const float*)d_in[10];
    const float* dwb   = (const float*)d_in[11];
    const float* g2    = (const float*)d_in[12];
    const float* bb2   = (const float*)d_in[13];
    const float* m2    = (const float*)d_in[14];
    const float* v2    = (const float*)d_in[15];
    const float* caw1  = (const float*)d_in[16];
    const float* cab1  = (const float*)d_in[17];
    const float* caw2  = (const float*)d_in[18];
    const float* cab2  = (const float*)d_in[19];
    const float* saw   = (const float*)d_in[20];
    const float* sag   = (const float*)d_in[21];
    const float* sab   = (const float*)d_in[22];
    const float* sam   = (const float*)d_in[23];
    const float* sav   = (const float*)d_in[24];
    const float* sepw  = (const float*)d_in[25];
    const float* sepb  = (const float*)d_in[26];
    const float* g3    = (const float*)d_in[27];
    const float* bb3   = (const float*)d_in[28];
    const float* m3    = (const float*)d_in[29];
    const float* v3    = (const float*)d_in[30];

    cudaFuncSetAttribute(k1_front, cudaFuncAttributeMaxDynamicSharedMemorySize,
                         SMEM_BYTES);

    dim3 grid1(NTILE, BB);
    k1_front<<<grid1, 1024, SMEM_BYTES>>>(x, ahat, w1, b1c, g1, bb1, m1, v1,
                                          gcw, gcb, dww, dwb, g2, bb2, m2, v2);

    dim3 grid2b(NTILE2, BB);
    k2b_attpool<<<grid2b, 256>>>(caw1, cab1, caw2, cab2, saw, sag, sab, sam, sav);

    k2c_tail<<<BB, 256>>>(sepw, sepb, g3, bb3, m3, v3, (float*)d_out);
}

// round 7
// speedup vs baseline: 1.4613x; 1.0179x over previous
#include <cuda_runtime.h>
#include <math.h>

// ---------------- problem constants ----------------
#define BB     16
#define F1N    16
#define CC     64
#define TTOT   1000
#define KK     64
#define C2N    32
#define PWN    16
#define EPSF   1e-5f

// ---------------- kernel-1 tiling ----------------
#define TILE   112         // time points per block
#define NTILE  9           // 9*112 = 1008 >= 1000 (last tile partial)
#define TSUB   16          // chunk of t per phase round (power of 2)
#define NCHUNK 7           // 7*16 = 112
#define XS_W   177         // TILE + 63 halo + 2 (odd -> conflict-free)
#define ES_S   17          // padded row stride for es (odd)

// smem float counts
#define NF_XS   (CC*XS_W)       // 11328
#define NF_WS   (F1N*KK)        // 1024
#define NF_AH   (CC*CC)         // 4096
#define NF_DW   (C2N*CC)        // 2048
#define NF_ES   (F1N*CC*ES_S)   // 17408
#define NF_XG   (CC*TSUB)       // 1024 (reused as stats stash)
#define NF_AX   (CC*TSUB)       // 1024
#define NF_SMALL 144
#define SMEM_FLOATS (NF_XS+NF_WS+NF_AH+NF_DW+NF_ES+NF_XG+NF_AX+NF_SMALL)
#define SMEM_BYTES  (SMEM_FLOATS*4)   // ~152 KB

// K2 tiling
#define K2B_W    8            // pool windows per k2b tile
#define K2B_T    (K2B_W*PWN)  // 128 t per tile
#define NTILE2   8            // 7 full + 1 partial (6 windows)
#define NPOOL    62           // 992/16

__device__ float g_h2[BB * C2N * TTOT];        // stage-3 output (2 MB)
__device__ float g_psum[BB * C2N * NTILE];     // per-tile sum partials
__device__ float g_pmax[BB * C2N * NTILE];     // per-tile max partials
__device__ float g_q[BB * C2N * NPOOL];        // pooled pre-sepconv

__device__ __forceinline__ float eluf(float v) { return v > 0.f ? v : expm1f(v); }
__device__ __forceinline__ float sigmf(float z) { return 1.f / (1.f + expf(-z)); }

// ============================================================
// Kernel 1: temporal conv + BN1 + ELU + GCN residual +
//           depthwise expansion + BN2 -> g_h2 (+ per-tile stats)
// grid (NTILE, BB) = 144 blocks (single wave), 1024 threads
// conv thread map: (f, c) -> 1 filter x 16 t per thread
// ============================================================
__global__ void __launch_bounds__(1024, 1)
k1_front(const float* __restrict__ x,
         const float* __restrict__ ahat_g,
         const float* __restrict__ w1,  const float* __restrict__ b1c,
         const float* __restrict__ g1,  const float* __restrict__ bb1,
         const float* __restrict__ m1,  const float* __restrict__ v1,
         const float* __restrict__ gcw, const float* __restrict__ gcb,
         const float* __restrict__ dww_g, const float* __restrict__ dwb,
         const float* __restrict__ g2,  const float* __restrict__ bb2,
         const float* __restrict__ m2,  const float* __restrict__ v2)
{
    extern __shared__ float sm[];
    float* xs  = sm;                 // [CC][XS_W]
    float* ws  = xs  + NF_XS;        // [F1][KK] (BN1-scaled weights)
    float* ah  = ws  + NF_WS;        // [CC][CC]
    float* dw  = ah  + NF_AH;        // [C2][CC]
    float* es  = dw  + NF_DW;        // [F1][CC][ES_S]
    float* xg  = es  + NF_ES;        // [CC][TSUB] (reused as stats stash)
    float* ax  = xg  + NF_XG;        // [CC][TSUB]
    float* o1s = ax  + NF_AX;        // [F1]
    float* gw  = o1s + F1N;          // [F1]
    float* s2  = gw  + F1N;          // [C2]
    float* sh2 = s2  + C2N;          // [C2]
    float* cst = sh2 + C2N;          // [C2]

    const int tid = threadIdx.x;
    const int b   = blockIdx.y;
    const int t0  = blockIdx.x * TILE;

    // ---- cooperative loads ----
    for (int i = tid; i < NF_XS; i += 1024) {
        int c = i / XS_W, j = i % XS_W;
        int tg = t0 - 31 + j;
        xs[i] = (tg >= 0 && tg < TTOT) ? x[(b * CC + c) * TTOT + tg] : 0.f;
    }
    for (int i = tid; i < NF_WS; i += 1024) {
        int f = i / KK;
        float s1 = g1[f] * rsqrtf(v1[f] + EPSF);
        ws[i] = w1[i] * s1;
    }
    for (int i = tid; i < NF_AH; i += 1024) ah[i] = ahat_g[i];
    for (int i = tid; i < NF_DW; i += 1024) dw[i] = dww_g[i];
    if (tid < F1N) {
        float s1 = g1[tid] * rsqrtf(v1[tid] + EPSF);
        o1s[tid] = b1c[tid] * s1 + bb1[tid] - m1[tid] * s1;
        gw[tid]  = gcw[tid];
    }
    if (tid < C2N) {
        float s = g2[tid] * rsqrtf(v2[tid] + EPSF);
        s2[tid]  = s;
        sh2[tid] = bb2[tid] - m2[tid] * s;
    }
    __syncthreads();
    if (tid < C2N) {
        float wsum = 0.f;
        for (int c = 0; c < CC; ++c) wsum += dw[tid * CC + c];
        cst[tid] = gcb[tid >> 1] * wsum + dwb[tid];
    }
    __syncthreads();

    // conv thread map: (f, c); warp spans 32 consecutive c (conflict-free)
    const int f = tid >> 6;           // 0..15
    const int c = tid & 63;
    const float* xrow = xs + c * XS_W;
    const float* wr   = ws + f * KK;
    float* erow = es + (f * CC + c) * ES_S;
    const float o1 = o1s[f];

    const int cc_idx = tid >> 4;      // for phases B/C (0..63)
    const int tt_idx = tid & 15;

    float stat_s = 0.f, stat_m = -INFINITY;

    for (int chk = 0; chk < NCHUNK; ++chk) {
        const int ct = chk * TSUB;

        // ---- phase A: conv + BN1 + ELU -> es ----
        {
            float acc[TSUB], win[TSUB];
            #pragma unroll
            for (int i = 0; i < TSUB; ++i) {
                acc[i] = 0.f;
                win[i] = xrow[ct + i];
            }
            int k = 0;
            #pragma unroll 1
            for (int m = 0; m < 4; ++m) {
                #pragma unroll
                for (int kk = 0; kk < 16; ++kk) {
                    float w = wr[k + kk];
                    #pragma unroll
                    for (int i = 0; i < TSUB; ++i)
                        acc[i] = fmaf(w, win[(kk + i) & 15], acc[i]);
                    win[kk] = xrow[ct + k + kk + TSUB];
                }
                k += 16;
            }
            #pragma unroll
            for (int i = 0; i < TSUB; ++i)
                erow[i] = eluf(acc[i] + o1);
        }
        __syncthreads();

        // ---- phase B: xg = mean_f es (1 item/thread) ----
        {
            float s = 0.f;
            #pragma unroll
            for (int ff = 0; ff < F1N; ++ff)
                s += es[(ff * CC + cc_idx) * ES_S + tt_idx];
            xg[cc_idx * TSUB + tt_idx] = s * (1.f / F1N);
        }
        __syncthreads();

        // ---- phase C: ax = a_hat @ xg (1 item/thread) ----
        {
            const float* ar = ah + cc_idx * CC;
            float s = 0.f;
            #pragma unroll 8
            for (int j = 0; j < CC; ++j)
                s = fmaf(ar[j], xg[j * TSUB + tt_idx], s);
            ax[cc_idx * TSUB + tt_idx] = s;
        }
        __syncthreads();

        // ---- phase D: depthwise expansion + GCN + BN2 -> g_h2 ----
        if (tid < C2N * TSUB) {
            int c2 = tid >> 4, tt = tid & 15;
            int ff = c2 >> 1;
            float gwf = gw[ff];
            const float* dr = dw + c2 * CC;
            float s = 0.f;
            #pragma unroll 8
            for (int cc = 0; cc < CC; ++cc)
                s = fmaf(dr[cc], es[(ff * CC + cc) * ES_S + tt] + gwf * ax[cc * TSUB + tt], s);
            float outv = (s + cst[c2]) * s2[c2] + sh2[c2];
            int t = t0 + ct + tt;
            if (t < TTOT) g_h2[(b * C2N + c2) * TTOT + t] = outv;
            xg[c2 * TSUB + tt] = outv;      // stash (xg dead after phase C)
        }
        __syncthreads();

        // ---- stats accumulate (threads 0..31, one c2 each) ----
        if (tid < C2N) {
            #pragma unroll
            for (int tt = 0; tt < TSUB; ++tt) {
                if (t0 + ct + tt < TTOT) {
                    float v = xg[tid * TSUB + tt];
                    stat_s += v; stat_m = fmaxf(stat_m, v);
                }
            }
        }
        __syncthreads();
    }

    if (tid < C2N) {
        g_psum[(b * C2N + tid) * NTILE + blockIdx.x] = stat_s;
        g_pmax[(b * C2N + tid) * NTILE + blockIdx.x] = stat_m;
    }
}

// ============================================================
// Kernel 2b: channel attn + spatial attn + ELU + pool16 -> g_q
// grid (NTILE2, BB), 256 threads
// ============================================================
#define H2S_S 131
__global__ void __launch_bounds__(256, 4)
k2b_attpool(const float* __restrict__ caw1, const float* __restrict__ cab1,
            const float* __restrict__ caw2, const float* __restrict__ cab2,
            const float* __restrict__ saw,
            const float* __restrict__ sag, const float* __restrict__ sab,
            const float* __restrict__ sam, const float* __restrict__ sav)
{
    __shared__ float att[C2N];
    __shared__ float h2s[C2N * H2S_S];
    __shared__ float mms[K2B_T + 2], mxs[K2B_T + 2], sgs[K2B_T];
    __shared__ float sstat[C2N];

    const int tile = blockIdx.x, b = blockIdx.y;
    const int tid  = threadIdx.x;
    const int t0   = tile * K2B_T;
    const int tw   = (tile == NTILE2 - 1) ? (NPOOL * PWN - t0) : K2B_T;
    const int nw   = tw / PWN;

    if (tid < C2N) {
        float s = 0.f, m = -INFINITY;
        const float* ps = g_psum + (b * C2N + tid) * NTILE;
        const float* pm = g_pmax + (b * C2N + tid) * NTILE;
        #pragma unroll
        for (int tl = 0; tl < NTILE; ++tl) {
            s += ps[tl]; m = fmaxf(m, pm[tl]);
        }
        sstat[tid] = s * (1.f / TTOT) + m;
    }
    __syncthreads();
    if (tid < C2N) {
        float r0 = cab1[0], r1 = cab1[1];
        for (int j = 0; j < C2N; ++j) {
            r0 += caw1[j] * sstat[j];
            r1 += caw1[C2N + j] * sstat[j];
        }
        r0 = fmaxf(r0, 0.f); r1 = fmaxf(r1, 0.f);
        att[tid] = sigmf(cab2[tid] + caw2[tid * 2] * r0 + caw2[tid * 2 + 1] * r1);
    }
    __syncthreads();

    const float* h2 = g_h2 + b * C2N * TTOT;
    for (int idx = tid; idx < C2N * (tw + 2); idx += 256) {
        int c2 = idx / (tw + 2), j = idx % (tw + 2);
        int t = t0 - 1 + j;
        float v = (t >= 0 && t < TTOT) ? h2[c2 * TTOT + t] * att[c2] : 0.f;
        h2s[c2 * H2S_S + j] = v;
    }
    __syncthreads();

    for (int j = tid; j < tw + 2; j += 256) {
        float s = 0.f, mx = -INFINITY;
        #pragma unroll 8
        for (int c2 = 0; c2 < C2N; ++c2) {
            float v = h2s[c2 * H2S_S + j];
            s += v; mx = fmaxf(mx, v);
        }
        mms[j] = s * (1.f / C2N);
        mxs[j] = mx;
    }
    __syncthreads();

    {
        float ssa = sag[0] * rsqrtf(sav[0] + EPSF);
        float sha = sab[0] - sam[0] * ssa;
        for (int j = tid; j < tw; j += 256) {
            int t = t0 + j;
            float acc = 0.f;
            #pragma unroll
            for (int kw = 0; kw < 3; ++kw) {
                int tt = t - 1 + kw;
                if (tt >= 0 && tt < TTOT)
                    acc += saw[3 + kw] * mms[j + kw] + saw[12 + kw] * mxs[j + kw];
            }
            sgs[j] = sigmf(acc * ssa + sha);
        }
    }
    __syncthreads();

    {
        int c2 = tid & 31, w = tid >> 5;
        if (w < nw) {
            float acc = 0.f;
            #pragma unroll
            for (int j = 0; j < PWN; ++j) {
                int tl = w * PWN + j;
                acc += eluf(h2s[c2 * H2S_S + tl + 1] * sgs[tl]);
            }
            g_q[(b * C2N + c2) * NPOOL + tile * K2B_W + w] = acc * (1.f / PWN);
        }
    }
}

// ============================================================
// Kernel 2c: depthwise sep conv + BN3 + ELU + pool16 -> out
// grid (BB), 256 threads — lane-group-of-16 parallel reduction
// ============================================================
__global__ void __launch_bounds__(256, 4)
k2c_tail(const float* __restrict__ sepw, const float* __restrict__ sepb,
         const float* __restrict__ g3, const float* __restrict__ bb3,
         const float* __restrict__ m3, const float* __restrict__ v3,
         float* __restrict__ out)
{
    __shared__ float qs[C2N * NPOOL];
    __shared__ float sw[C2N * PWN];
    const int b = blockIdx.x, tid = threadIdx.x;
    for (int i = tid; i < C2N * NPOOL; i += 256)
        qs[i] = g_q[b * C2N * NPOOL + i];
    for (int i = tid; i < C2N * PWN; i += 256)
        sw[i] = sepw[i];
    __syncthreads();

    const int j  = tid & 15;
    const int e0 = tid >> 4;
    for (int r = 0; r < 6; ++r) {
        int e  = e0 + r * 16;          // 0..95 = c2*3 + to
        int c2 = e / 3, to = e % 3;
        int t  = to * PWN + j;
        float y = sepb[c2];
        #pragma unroll
        for (int u = 0; u < PWN; ++u) {
            int tq = t - 7 + u;
            if (tq >= 0 && tq < NPOOL) y = fmaf(sw[c2 * PWN + u], qs[c2 * NPOOL + tq], y);
        }
        float s3  = g3[c2] * rsqrtf(v3[c2] + EPSF);
        float sh3 = bb3[c2] - m3[c2] * s3;
        float v = eluf(y * s3 + sh3);
        #pragma unroll
        for (int o = 8; o > 0; o >>= 1)
            v += __shfl_down_sync(0xffffffffu, v, o, 16);
        if (j == 0) out[b * (C2N * 3) + e] = v * (1.f / PWN);
    }
}

// ============================================================
extern "C" void kernel_launch(void* const* d_in, const int* in_sizes, int n_in,
                              void* d_out, int out_size)
{
    const float* x     = (const float*)d_in[0];
    const float* ahat  = (const float*)d_in[1];
    const float* w1    = (const float*)d_in[2];
    const float* b1c   = (const float*)d_in[3];
    const float* g1    = (const float*)d_in[4];
    const float* bb1   = (const float*)d_in[5];
    const float* m1    = (const float*)d_in[6];
    const float* v1    = (const float*)d_in[7];
    const float* gcw   = (const float*)d_in[8];
    const float* gcb   = (const float*)d_in[9];
    const float* dww   = (const float*)d_in[10];
    const float* dwb   = (const float*)d_in[11];
    const float* g2    = (const float*)d_in[12];
    const float* bb2   = (const float*)d_in[13];
    const float* m2    = (const float*)d_in[14];
    const float* v2    = (const float*)d_in[15];
    const float* caw1  = (const float*)d_in[16];
    const float* cab1  = (const float*)d_in[17];
    const float* caw2  = (const float*)d_in[18];
    const float* cab2  = (const float*)d_in[19];
    const float* saw   = (const float*)d_in[20];
    const float* sag   = (const float*)d_in[21];
    const float* sab   = (const float*)d_in[22];
    const float* sam   = (const float*)d_in[23];
    const float* sav   = (const float*)d_in[24];
    const float* sepw  = (const float*)d_in[25];
    const float* sepb  = (const float*)d_in[26];
    const float* g3    = (const float*)d_in[27];
    const float* bb3   = (const float*)d_in[28];
    const float* m3    = (const float*)d_in[29];
    const float* v3    = (const float*)d_in[30];

    cudaFuncSetAttribute(k1_front, cudaFuncAttributeMaxDynamicSharedMemorySize,
                         SMEM_BYTES);

    dim3 grid1(NTILE, BB);
    k1_front<<<grid1, 1024, SMEM_BYTES>>>(x, ahat, w1, b1c, g1, bb1, m1, v1,
                                          gcw, gcb, dww, dwb, g2, bb2, m2, v2);

    dim3 grid2b(NTILE2, BB);
    k2b_attpool<<<grid2b, 256>>>(caw1, cab1, caw2, cab2, saw, sag, sab, sam, sav);

    k2c_tail<<<BB, 256>>>(sepw, sepb, g3, bb3, m3, v3, (float*)d_out);
}

// round 8
// speedup vs baseline: 1.4901x; 1.0197x over previous
#include <cuda_runtime.h>
#include <math.h>

// ---------------- problem constants ----------------
#define BB     16
#define F1N    16
#define CC     64
#define TTOT   1000
#define KK     64
#define C2N    32
#define PWN    16
#define EPSF   1e-5f

// ---------------- kernel-1 tiling ----------------
#define TILE   112         // time points per block
#define NTILE  9           // 9*112 = 1008 >= 1000 (last tile partial)
#define TSUB   16          // chunk of t per phase round (power of 2)
#define NCHUNK 7           // 7*16 = 112
#define XS_W   177         // TILE + 63 halo + 2 (odd -> conflict-free)
#define ES_S   17          // padded row stride for es (odd)

// smem float counts
#define NF_XS   (CC*XS_W)       // 11328
#define NF_WS   (F1N*KK)        // 1024
#define NF_AH   (CC*CC)         // 4096
#define NF_DW   (C2N*CC)        // 2048
#define NF_ES   (F1N*CC*ES_S)   // 17408
#define NF_XG   (CC*TSUB)       // 1024
#define NF_AX   (CC*TSUB)       // 1024
#define NF_SMALL 144
#define SMEM_FLOATS (NF_XS+NF_WS+NF_AH+NF_DW+NF_ES+NF_XG+NF_AX+NF_SMALL)
#define SMEM_BYTES  (SMEM_FLOATS*4)   // ~149 KB

// K2 tiling
#define K2B_W    8            // pool windows per k2b tile
#define K2B_T    (K2B_W*PWN)  // 128 t per tile
#define NTILE2   8            // 7 full + 1 partial (6 windows)
#define NPOOL    62           // 992/16

__device__ float g_h2[BB * C2N * TTOT];        // stage-3 output (2 MB)
__device__ float g_psum[BB * C2N * NTILE];     // per-tile sum partials
__device__ float g_pmax[BB * C2N * NTILE];     // per-tile max partials
__device__ float g_q[BB * C2N * NPOOL];        // pooled pre-sepconv

__device__ __forceinline__ float eluf(float v) { return v > 0.f ? v : expm1f(v); }
__device__ __forceinline__ float sigmf(float z) { return 1.f / (1.f + expf(-z)); }

// ============================================================
// Kernel 1: temporal conv + BN1 + ELU + GCN residual +
//           depthwise expansion + BN2 -> g_h2 (+ per-tile stats)
// grid (NTILE, BB) = 144 blocks (single wave), 1024 threads
// ============================================================
__global__ void __launch_bounds__(1024, 1)
k1_front(const float* __restrict__ x,
         const float* __restrict__ ahat_g,
         const float* __restrict__ w1,  const float* __restrict__ b1c,
         const float* __restrict__ g1,  const float* __restrict__ bb1,
         const float* __restrict__ m1,  const float* __restrict__ v1,
         const float* __restrict__ gcw, const float* __restrict__ gcb,
         const float* __restrict__ dww_g, const float* __restrict__ dwb,
         const float* __restrict__ g2,  const float* __restrict__ bb2,
         const float* __restrict__ m2,  const float* __restrict__ v2)
{
    extern __shared__ float sm[];
    float* xs  = sm;                 // [CC][XS_W]
    float* ws  = xs  + NF_XS;        // [F1][KK] (BN1-scaled weights)
    float* ah  = ws  + NF_WS;        // [CC][CC]   (16B aligned)
    float* dw  = ah  + NF_AH;        // [C2][CC]   (16B aligned)
    float* es  = dw  + NF_DW;        // [F1][CC][ES_S]
    float* xg  = es  + NF_ES;        // [CC][TSUB]
    float* ax  = xg  + NF_XG;        // [CC][TSUB]
    float* o1s = ax  + NF_AX;        // [F1]
    float* gw  = o1s + F1N;          // [F1]
    float* s2  = gw  + F1N;          // [C2]
    float* sh2 = s2  + C2N;          // [C2]
    float* cst = sh2 + C2N;          // [C2]

    const int tid = threadIdx.x;
    const int b   = blockIdx.y;
    const int t0  = blockIdx.x * TILE;

    // ---- cooperative loads ----
    for (int i = tid; i < NF_XS; i += 1024) {
        int c = i / XS_W, j = i % XS_W;
        int tg = t0 - 31 + j;
        xs[i] = (tg >= 0 && tg < TTOT) ? x[(b * CC + c) * TTOT + tg] : 0.f;
    }
    for (int i = tid; i < NF_WS; i += 1024) {
        int f = i / KK;
        float s1 = g1[f] * rsqrtf(v1[f] + EPSF);
        ws[i] = w1[i] * s1;
    }
    for (int i = tid; i < NF_AH; i += 1024) ah[i] = ahat_g[i];
    for (int i = tid; i < NF_DW; i += 1024) dw[i] = dww_g[i];
    if (tid < F1N) {
        float s1 = g1[tid] * rsqrtf(v1[tid] + EPSF);
        o1s[tid] = b1c[tid] * s1 + bb1[tid] - m1[tid] * s1;
        gw[tid]  = gcw[tid];
    }
    if (tid < C2N) {
        float s = g2[tid] * rsqrtf(v2[tid] + EPSF);
        s2[tid]  = s;
        sh2[tid] = bb2[tid] - m2[tid] * s;
    }
    __syncthreads();
    if (tid < C2N) {
        float wsum = 0.f;
        for (int c = 0; c < CC; ++c) wsum += dw[tid * CC + c];
        cst[tid] = gcb[tid >> 1] * wsum + dwb[tid];
    }
    __syncthreads();

    // conv thread map: (f, c); warp spans 32 consecutive c (conflict-free)
    const int f = tid >> 6;           // 0..15
    const int c = tid & 63;
    const float* xrow = xs + c * XS_W;
    const float* wr   = ws + f * KK;
    float* erow = es + (f * CC + c) * ES_S;
    const float o1 = o1s[f];

    const int cc_idx = tid >> 4;      // for phases B/C (0..63)
    const int tt_idx = tid & 15;

    float stat_s = 0.f, stat_m = -INFINITY;

    for (int chk = 0; chk < NCHUNK; ++chk) {
        const int ct = chk * TSUB;

        // ---- phase A: conv + BN1 + ELU -> es ----
        {
            float acc[TSUB], win[TSUB];
            #pragma unroll
            for (int i = 0; i < TSUB; ++i) {
                acc[i] = 0.f;
                win[i] = xrow[ct + i];
            }
            int k = 0;
            #pragma unroll 1
            for (int m = 0; m < 4; ++m) {
                #pragma unroll
                for (int kk = 0; kk < 16; ++kk) {
                    float w = wr[k + kk];
                    #pragma unroll
                    for (int i = 0; i < TSUB; ++i)
                        acc[i] = fmaf(w, win[(kk + i) & 15], acc[i]);
                    win[kk] = xrow[ct + k + kk + TSUB];
                }
                k += 16;
            }
            #pragma unroll
            for (int i = 0; i < TSUB; ++i)
                erow[i] = eluf(acc[i] + o1);
        }
        __syncthreads();

        // ---- phase B: xg = mean_f es (1 item/thread) ----
        {
            float s = 0.f;
            #pragma unroll
            for (int ff = 0; ff < F1N; ++ff)
                s += es[(ff * CC + cc_idx) * ES_S + tt_idx];
            xg[cc_idx * TSUB + tt_idx] = s * (1.f / F1N);
        }
        __syncthreads();

        // ---- phase C: ax = a_hat @ xg (1 item/thread, float4 rows) ----
        {
            const float4* ar4 = (const float4*)(ah + cc_idx * CC);
            float s = 0.f;
            #pragma unroll
            for (int q = 0; q < 16; ++q) {
                float4 a = ar4[q];
                int j = q * 4;
                s = fmaf(a.x, xg[(j + 0) * TSUB + tt_idx], s);
                s = fmaf(a.y, xg[(j + 1) * TSUB + tt_idx], s);
                s = fmaf(a.z, xg[(j + 2) * TSUB + tt_idx], s);
                s = fmaf(a.w, xg[(j + 3) * TSUB + tt_idx], s);
            }
            ax[cc_idx * TSUB + tt_idx] = s;
        }
        __syncthreads();

        // ---- phase D: depthwise expansion + GCN + BN2 -> g_h2
        //      + fused stats (16-lane shfl; lanes 0-15 share c2) ----
        if (tid < C2N * TSUB) {
            int c2 = tid >> 4, tt = tid & 15;
            int ff = c2 >> 1;
            float gwf = gw[ff];
            const float4* dr4 = (const float4*)(dw + c2 * CC);
            const float* er = es + ff * CC * ES_S + tt;
            const float* axr = ax + tt;
            float s = 0.f;
            #pragma unroll
            for (int q = 0; q < 16; ++q) {
                float4 d = dr4[q];
                int cc = q * 4;
                s = fmaf(d.x, fmaf(gwf, axr[(cc + 0) * TSUB], er[(cc + 0) * ES_S]), s);
                s = fmaf(d.y, fmaf(gwf, axr[(cc + 1) * TSUB], er[(cc + 1) * ES_S]), s);
                s = fmaf(d.z, fmaf(gwf, axr[(cc + 2) * TSUB], er[(cc + 2) * ES_S]), s);
                s = fmaf(d.w, fmaf(gwf, axr[(cc + 3) * TSUB], er[(cc + 3) * ES_S]), s);
            }
            float outv = (s + cst[c2]) * s2[c2] + sh2[c2];
            int t = t0 + ct + tt;
            bool valid = (t < TTOT);
            if (valid) g_h2[(b * C2N + c2) * TTOT + t] = outv;
            float sv = valid ? outv : 0.f;
            float mv = valid ? outv : -INFINITY;
            #pragma unroll
            for (int o = 8; o > 0; o >>= 1) {
                sv += __shfl_down_sync(0xffffffffu, sv, o, 16);
                mv  = fmaxf(mv, __shfl_down_sync(0xffffffffu, mv, o, 16));
            }
            if (tt == 0) { stat_s += sv; stat_m = fmaxf(stat_m, mv); }
        }
        __syncthreads();
    }

    if (tid < C2N * TSUB && (tid & 15) == 0) {
        int c2 = tid >> 4;
        g_psum[(b * C2N + c2) * NTILE + blockIdx.x] = stat_s;
        g_pmax[(b * C2N + c2) * NTILE + blockIdx.x] = stat_m;
    }
}

// ============================================================
// Kernel 2b: channel attn + spatial attn + ELU + pool16 -> g_q
// grid (NTILE2, BB), 256 threads
// ============================================================
#define H2S_S 131
__global__ void __launch_bounds__(256, 4)
k2b_attpool(const float* __restrict__ caw1, const float* __restrict__ cab1,
            const float* __restrict__ caw2, const float* __restrict__ cab2,
            const float* __restrict__ saw,
            const float* __restrict__ sag, const float* __restrict__ sab,
            const float* __restrict__ sam, const float* __restrict__ sav)
{
    __shared__ float att[C2N];
    __shared__ float h2s[C2N * H2S_S];
    __shared__ float mms[K2B_T + 2], mxs[K2B_T + 2], sgs[K2B_T];
    __shared__ float sstat[C2N];

    const int tile = blockIdx.x, b = blockIdx.y;
    const int tid  = threadIdx.x;
    const int t0   = tile * K2B_T;
    const int tw   = (tile == NTILE2 - 1) ? (NPOOL * PWN - t0) : K2B_T;
    const int nw   = tw / PWN;

    if (tid < C2N) {
        float s = 0.f, m = -INFINITY;
        const float* ps = g_psum + (b * C2N + tid) * NTILE;
        const float* pm = g_pmax + (b * C2N + tid) * NTILE;
        #pragma unroll
        for (int tl = 0; tl < NTILE; ++tl) {
            s += ps[tl]; m = fmaxf(m, pm[tl]);
        }
        sstat[tid] = s * (1.f / TTOT) + m;
    }
    __syncthreads();
    if (tid < C2N) {
        float r0 = cab1[0], r1 = cab1[1];
        for (int j = 0; j < C2N; ++j) {
            r0 += caw1[j] * sstat[j];
            r1 += caw1[C2N + j] * sstat[j];
        }
        r0 = fmaxf(r0, 0.f); r1 = fmaxf(r1, 0.f);
        att[tid] = sigmf(cab2[tid] + caw2[tid * 2] * r0 + caw2[tid * 2 + 1] * r1);
    }
    __syncthreads();

    const float* h2 = g_h2 + b * C2N * TTOT;
    for (int idx = tid; idx < C2N * (tw + 2); idx += 256) {
        int c2 = idx / (tw + 2), j = idx % (tw + 2);
        int t = t0 - 1 + j;
        float v = (t >= 0 && t < TTOT) ? h2[c2 * TTOT + t] * att[c2] : 0.f;
        h2s[c2 * H2S_S + j] = v;
    }
    __syncthreads();

    for (int j = tid; j < tw + 2; j += 256) {
        float s = 0.f, mx = -INFINITY;
        #pragma unroll 8
        for (int c2 = 0; c2 < C2N; ++c2) {
            float v = h2s[c2 * H2S_S + j];
            s += v; mx = fmaxf(mx, v);
        }
        mms[j] = s * (1.f / C2N);
        mxs[j] = mx;
    }
    __syncthreads();

    {
        float ssa = sag[0] * rsqrtf(sav[0] + EPSF);
        float sha = sab[0] - sam[0] * ssa;
        for (int j = tid; j < tw; j += 256) {
            int t = t0 + j;
            float acc = 0.f;
            #pragma unroll
            for (int kw = 0; kw < 3; ++kw) {
                int tt = t - 1 + kw;
                if (tt >= 0 && tt < TTOT)
                    acc += saw[3 + kw] * mms[j + kw] + saw[12 + kw] * mxs[j + kw];
            }
            sgs[j] = sigmf(acc * ssa + sha);
        }
    }
    __syncthreads();

    {
        int c2 = tid & 31, w = tid >> 5;
        if (w < nw) {
            float acc = 0.f;
            #pragma unroll
            for (int j = 0; j < PWN; ++j) {
                int tl = w * PWN + j;
                acc += eluf(h2s[c2 * H2S_S + tl + 1] * sgs[tl]);
            }
            g_q[(b * C2N + c2) * NPOOL + tile * K2B_W + w] = acc * (1.f / PWN);
        }
    }
}

// ============================================================
// Kernel 2c: depthwise sep conv + BN3 + ELU + pool16 -> out
// grid (BB), 256 threads — lane-group-of-16 parallel reduction
// ============================================================
__global__ void __launch_bounds__(256, 4)
k2c_tail(const float* __restrict__ sepw, const float* __restrict__ sepb,
         const float* __restrict__ g3, const float* __restrict__ bb3,
         const float* __restrict__ m3, const float* __restrict__ v3,
         float* __restrict__ out)
{
    __shared__ float qs[C2N * NPOOL];
    __shared__ float sw[C2N * PWN];
    const int b = blockIdx.x, tid = threadIdx.x;
    for (int i = tid; i < C2N * NPOOL; i += 256)
        qs[i] = g_q[b * C2N * NPOOL + i];
    for (int i = tid; i < C2N * PWN; i += 256)
        sw[i] = sepw[i];
    __syncthreads();

    const int j  = tid & 15;
    const int e0 = tid >> 4;
    for (int r = 0; r < 6; ++r) {
        int e  = e0 + r * 16;          // 0..95 = c2*3 + to
        int c2 = e / 3, to = e % 3;
        int t  = to * PWN + j;
        float y = sepb[c2];
        #pragma unroll
        for (int u = 0; u < PWN; ++u) {
            int tq = t - 7 + u;
            if (tq >= 0 && tq < NPOOL) y = fmaf(sw[c2 * PWN + u], qs[c2 * NPOOL + tq], y);
        }
        float s3  = g3[c2] * rsqrtf(v3[c2] + EPSF);
        float sh3 = bb3[c2] - m3[c2] * s3;
        float v = eluf(y * s3 + sh3);
        #pragma unroll
        for (int o = 8; o > 0; o >>= 1)
            v += __shfl_down_sync(0xffffffffu, v, o, 16);
        if (j == 0) out[b * (C2N * 3) + e] = v * (1.f / PWN);
    }
}

// ============================================================
extern "C" void kernel_launch(void* const* d_in, const int* in_sizes, int n_in,
                              void* d_out, int out_size)
{
    const float* x     = (const float*)d_in[0];
    const float* ahat  = (const float*)d_in[1];
    const float* w1    = (const float*)d_in[2];
    const float* b1c   = (const float*)d_in[3];
    const float* g1    = (const float*)d_in[4];
    const float* bb1   = (const float*)d_in[5];
    const float* m1    = (const float*)d_in[6];
    const float* v1    = (const float*)d_in[7];
    const float* gcw   = (const float*)d_in[8];
    const float* gcb   = (const float*)d_in[9];
    const float* dww   = (const float*)d_in[10];
    const float* dwb   = (const float*)d_in[11];
    const float* g2    = (const float*)d_in[12];
    const float* bb2   = (const float*)d_in[13];
    const float* m2    = (const float*)d_in[14];
    const float* v2    = (const float*)d_in[15];
    const float* caw1  = (const float*)d_in[16];
    const float* cab1  = (const float*)d_in[17];
    const float* caw2  = (const float*)d_in[18];
    const float* cab2  = (const float*)d_in[19];
    const float* saw   = (const float*)d_in[20];
    const float* sag   = (const float*)d_in[21];
    const float* sab   = (const float*)d_in[22];
    const float* sam   = (const float*)d_in[23];
    const float* sav   = (const float*)d_in[24];
    const float* sepw  = (const float*)d_in[25];
    const float* sepb  = (const float*)d_in[26];
    const float* g3    = (const float*)d_in[27];
    const float* bb3   = (const float*)d_in[28];
    const float* m3    = (const float*)d_in[29];
    const float* v3    = (const float*)d_in[30];

    cudaFuncSetAttribute(k1_front, cudaFuncAttributeMaxDynamicSharedMemorySize,
                         SMEM_BYTES);

    dim3 grid1(NTILE, BB);
    k1_front<<<grid1, 1024, SMEM_BYTES>>>(x, ahat, w1, b1c, g1, bb1, m1, v1,
                                          gcw, gcb, dww, dwb, g2, bb2, m2, v2);

    dim3 grid2b(NTILE2, BB);
    k2b_attpool<<<grid2b, 256>>>(caw1, cab1, caw2, cab2, saw, sag, sab, sam, sav);

    k2c_tail<<<BB, 256>>>(sepw, sepb, g3, bb3, m3, v3, (float*)d_out);
}

// round 9
// speedup vs baseline: 1.5869x; 1.0650x over previous
#include <cuda_runtime.h>
#include <math.h>

// ---------------- problem constants ----------------
#define BB     16
#define F1N    16
#define CC     64
#define TTOT   1000
#define KK     64
#define C2N    32
#define PWN    16
#define EPSF   1e-5f

// ---------------- kernel-1 tiling ----------------
#define TILE   112         // time points per block
#define NTILE  9           // 9*112 = 1008 >= 1000 (last tile partial)
#define TSUB   16          // chunk of t per phase round (power of 2)
#define NCHUNK 7           // 7*16 = 112
#define XS_W   177         // TILE + 63 halo + 2 (odd -> conflict-free)
#define ES_S   17          // padded row stride for es (odd)

// smem float counts
#define NF_XS   (CC*XS_W)       // 11328
#define NF_WS   (F1N*KK)        // 1024
#define NF_AH   (CC*CC)         // 4096
#define NF_DW   (C2N*CC)        // 2048
#define NF_ES   (F1N*CC*ES_S)   // 17408
#define NF_XG   (CC*TSUB)       // 1024
#define NF_M0   (C2N*CC)        // 2048
#define NF_PS   (C2N*TSUB)      // 512
#define NF_SMALL 144
#define SMEM_FLOATS (NF_XS+NF_WS+NF_AH+NF_DW+NF_ES+NF_XG+NF_M0+NF_PS+NF_SMALL)
#define SMEM_BYTES  (SMEM_FLOATS*4)   // ~158 KB

// K2 tiling
#define K2B_W    8            // pool windows per k2b tile
#define K2B_T    (K2B_W*PWN)  // 128 t per tile
#define NTILE2   8            // 7 full + 1 partial (6 windows)
#define NPOOL    62           // 992/16

__device__ float g_h2[BB * C2N * TTOT];        // stage-3 output (2 MB)
__device__ float g_psum[BB * C2N * NTILE];     // per-tile sum partials
__device__ float g_pmax[BB * C2N * NTILE];     // per-tile max partials
__device__ float g_q[BB * C2N * NPOOL];        // pooled pre-sepconv

__device__ __forceinline__ float eluf(float v) { return v > 0.f ? v : expm1f(v); }
__device__ __forceinline__ float sigmf(float z) { return 1.f / (1.f + expf(-z)); }

// ============================================================
// Kernel 1: temporal conv + BN1 + ELU + GCN residual +
//           depthwise expansion + BN2 -> g_h2 (+ per-tile stats)
// grid (NTILE, BB) = 144 blocks (single wave), 1024 threads
// Algebra: out[c2,t] = Sum_cc dw[c2,cc]*es[f,cc,t]
//                    + Sum_j M0[c2,j]*xg_raw[j,t] + cst[c2]
// where M0 = (gw[f]/F1) * dw @ ahat  (precomputed per block)
// ============================================================
__global__ void __launch_bounds__(1024, 1)
k1_front(const float* __restrict__ x,
         const float* __restrict__ ahat_g,
         const float* __restrict__ w1,  const float* __restrict__ b1c,
         const float* __restrict__ g1,  const float* __restrict__ bb1,
         const float* __restrict__ m1,  const float* __restrict__ v1,
         const float* __restrict__ gcw, const float* __restrict__ gcb,
         const float* __restrict__ dww_g, const float* __restrict__ dwb,
         const float* __restrict__ g2,  const float* __restrict__ bb2,
         const float* __restrict__ m2,  const float* __restrict__ v2)
{
    extern __shared__ float sm[];
    float* xs  = sm;                 // [CC][XS_W]
    float* ws  = xs  + NF_XS;        // [F1][KK] (BN1-scaled weights)
    float* ah  = ws  + NF_WS;        // [CC][CC]
    float* dw  = ah  + NF_AH;        // [C2][CC]   (16B aligned)
    float* es  = dw  + NF_DW;        // [F1][CC][ES_S]
    float* xg  = es  + NF_ES;        // [CC][TSUB] raw f-sum
    float* m0  = xg  + NF_XG;        // [C2][CC]   (16B aligned)
    float* ps  = m0  + NF_M0;        // [C2][TSUB] dw.es partials
    float* o1s = ps  + NF_PS;        // [F1]
    float* gw  = o1s + F1N;          // [F1]
    float* s2  = gw  + F1N;          // [C2]
    float* sh2 = s2  + C2N;          // [C2]
    float* cst = sh2 + C2N;          // [C2]

    const int tid = threadIdx.x;
    const int b   = blockIdx.y;
    const int t0  = blockIdx.x * TILE;

    // ---- cooperative loads ----
    for (int i = tid; i < NF_XS; i += 1024) {
        int c = i / XS_W, j = i % XS_W;
        int tg = t0 - 31 + j;
        xs[i] = (tg >= 0 && tg < TTOT) ? x[(b * CC + c) * TTOT + tg] : 0.f;
    }
    for (int i = tid; i < NF_WS; i += 1024) {
        int f = i / KK;
        float s1 = g1[f] * rsqrtf(v1[f] + EPSF);
        ws[i] = w1[i] * s1;
    }
    for (int i = tid; i < NF_AH; i += 1024) ah[i] = ahat_g[i];
    for (int i = tid; i < NF_DW; i += 1024) dw[i] = dww_g[i];
    if (tid < F1N) {
        float s1 = g1[tid] * rsqrtf(v1[tid] + EPSF);
        o1s[tid] = b1c[tid] * s1 + bb1[tid] - m1[tid] * s1;
        gw[tid]  = gcw[tid];
    }
    if (tid < C2N) {
        float s = g2[tid] * rsqrtf(v2[tid] + EPSF);
        s2[tid]  = s;
        sh2[tid] = bb2[tid] - m2[tid] * s;
    }
    __syncthreads();
    if (tid < C2N) {
        float wsum = 0.f;
        for (int c = 0; c < CC; ++c) wsum += dw[tid * CC + c];
        cst[tid] = gcb[tid >> 1] * wsum + dwb[tid];
    }
    // ---- precompute M0 = (gw/F1) * dw @ ahat  (2 items/thread) ----
    for (int it = tid; it < C2N * CC; it += 1024) {
        int c2 = it >> 6, j = it & 63;
        const float* dr = dw + c2 * CC;
        float s = 0.f;
        #pragma unroll 8
        for (int cc = 0; cc < CC; ++cc)
            s = fmaf(dr[cc], ah[cc * CC + j], s);
        m0[it] = s * gw[c2 >> 1] * (1.f / F1N);
    }
    __syncthreads();

    // conv thread map: (f, c); warp spans 32 consecutive c (conflict-free)
    const int f = tid >> 6;           // 0..15
    const int c = tid & 63;
    const float* xrow = xs + c * XS_W;
    const float* wr   = ws + f * KK;
    float* erow = es + (f * CC + c) * ES_S;
    const float o1 = o1s[f];

    float stat_s = 0.f, stat_m = -INFINITY;

    for (int chk = 0; chk < NCHUNK; ++chk) {
        const int ct = chk * TSUB;

        // ---- phase A: conv + BN1 + ELU -> es ----
        {
            float acc[TSUB], win[TSUB];
            #pragma unroll
            for (int i = 0; i < TSUB; ++i) {
                acc[i] = 0.f;
                win[i] = xrow[ct + i];
            }
            int k = 0;
            #pragma unroll 1
            for (int m = 0; m < 4; ++m) {
                #pragma unroll
                for (int kk = 0; kk < 16; ++kk) {
                    float w = wr[k + kk];
                    #pragma unroll
                    for (int i = 0; i < TSUB; ++i)
                        acc[i] = fmaf(w, win[(kk + i) & 15], acc[i]);
                    win[kk] = xrow[ct + k + kk + TSUB];
                }
                k += 16;
            }
            #pragma unroll
            for (int i = 0; i < TSUB; ++i)
                erow[i] = eluf(acc[i] + o1);
        }
        __syncthreads();

        // ---- phase 2 (split block):
        //      lower 512: ps[c2,tt] = Sum_cc dw[c2,cc]*es[f,cc,tt]
        //      upper 512: xg[cc,tt] = Sum_f es[f,cc,tt]  (2 items each)
        if (tid < C2N * TSUB) {
            int c2 = tid >> 4, tt = tid & 15;
            int ff = c2 >> 1;
            const float4* dr4 = (const float4*)(dw + c2 * CC);
            const float* er = es + ff * CC * ES_S + tt;
            float s = 0.f;
            #pragma unroll
            for (int q = 0; q < 16; ++q) {
                float4 d = dr4[q];
                int cc = q * 4;
                s = fmaf(d.x, er[(cc + 0) * ES_S], s);
                s = fmaf(d.y, er[(cc + 1) * ES_S], s);
                s = fmaf(d.z, er[(cc + 2) * ES_S], s);
                s = fmaf(d.w, er[(cc + 3) * ES_S], s);
            }
            ps[tid] = s;
        } else {
            int base = tid - 512;
            #pragma unroll
            for (int r = 0; r < 2; ++r) {
                int item = base + r * 512;
                int cc = item >> 4, tt = item & 15;
                const float* er = es + cc * ES_S + tt;
                float s = 0.f;
                #pragma unroll
                for (int ff = 0; ff < F1N; ++ff)
                    s += er[ff * CC * ES_S];
                xg[item] = s;
            }
        }
        __syncthreads();

        // ---- phase 3: combine + BN2 -> g_h2 + fused stats ----
        if (tid < C2N * TSUB) {
            int c2 = tid >> 4, tt = tid & 15;
            const float4* mr4 = (const float4*)(m0 + c2 * CC);
            const float* xr = xg + tt;
            float s = ps[tid];
            #pragma unroll
            for (int q = 0; q < 16; ++q) {
                float4 m = mr4[q];
                int j = q * 4;
                s = fmaf(m.x, xr[(j + 0) * TSUB], s);
                s = fmaf(m.y, xr[(j + 1) * TSUB], s);
                s = fmaf(m.z, xr[(j + 2) * TSUB], s);
                s = fmaf(m.w, xr[(j + 3) * TSUB], s);
            }
            float outv = (s + cst[c2]) * s2[c2] + sh2[c2];
            int t = t0 + chk * TSUB + tt;
            bool valid = (t < TTOT);
            if (valid) g_h2[(b * C2N + c2) * TTOT + t] = outv;
            float sv = valid ? outv : 0.f;
            float mv = valid ? outv : -INFINITY;
            #pragma unroll
            for (int o = 8; o > 0; o >>= 1) {
                sv += __shfl_down_sync(0xffffffffu, sv, o, 16);
                mv  = fmaxf(mv, __shfl_down_sync(0xffffffffu, mv, o, 16));
            }
            if (tt == 0) { stat_s += sv; stat_m = fmaxf(stat_m, mv); }
        }
        __syncthreads();
    }

    if (tid < C2N * TSUB && (tid & 15) == 0) {
        int c2 = tid >> 4;
        g_psum[(b * C2N + c2) * NTILE + blockIdx.x] = stat_s;
        g_pmax[(b * C2N + c2) * NTILE + blockIdx.x] = stat_m;
    }
}

// ============================================================
// Kernel 2b: channel attn + spatial attn + ELU + pool16 -> g_q
// grid (NTILE2, BB), 256 threads
// ============================================================
#define H2S_S 131
__global__ void __launch_bounds__(256, 4)
k2b_attpool(const float* __restrict__ caw1, const float* __restrict__ cab1,
            const float* __restrict__ caw2, const float* __restrict__ cab2,
            const float* __restrict__ saw,
            const float* __restrict__ sag, const float* __restrict__ sab,
            const float* __restrict__ sam, const float* __restrict__ sav)
{
    __shared__ float att[C2N];
    __shared__ float h2s[C2N * H2S_S];
    __shared__ float mms[K2B_T + 2], mxs[K2B_T + 2], sgs[K2B_T];
    __shared__ float sstat[C2N];

    const int tile = blockIdx.x, b = blockIdx.y;
    const int tid  = threadIdx.x;
    const int t0   = tile * K2B_T;
    const int tw   = (tile == NTILE2 - 1) ? (NPOOL * PWN - t0) : K2B_T;
    const int nw   = tw / PWN;

    if (tid < C2N) {
        float s = 0.f, m = -INFINITY;
        const float* pss = g_psum + (b * C2N + tid) * NTILE;
        const float* pm = g_pmax + (b * C2N + tid) * NTILE;
        #pragma unroll
        for (int tl = 0; tl < NTILE; ++tl) {
            s += pss[tl]; m = fmaxf(m, pm[tl]);
        }
        sstat[tid] = s * (1.f / TTOT) + m;
    }
    __syncthreads();
    if (tid < C2N) {
        float r0 = cab1[0], r1 = cab1[1];
        for (int j = 0; j < C2N; ++j) {
            r0 += caw1[j] * sstat[j];
            r1 += caw1[C2N + j] * sstat[j];
        }
        r0 = fmaxf(r0, 0.f); r1 = fmaxf(r1, 0.f);
        att[tid] = sigmf(cab2[tid] + caw2[tid * 2] * r0 + caw2[tid * 2 + 1] * r1);
    }
    __syncthreads();

    const float* h2 = g_h2 + b * C2N * TTOT;
    for (int idx = tid; idx < C2N * (tw + 2); idx += 256) {
        int c2 = idx / (tw + 2), j = idx % (tw + 2);
        int t = t0 - 1 + j;
        float v = (t >= 0 && t < TTOT) ? h2[c2 * TTOT + t] * att[c2] : 0.f;
        h2s[c2 * H2S_S + j] = v;
    }
    __syncthreads();

    for (int j = tid; j < tw + 2; j += 256) {
        float s = 0.f, mx = -INFINITY;
        #pragma unroll 8
        for (int c2 = 0; c2 < C2N; ++c2) {
            float v = h2s[c2 * H2S_S + j];
            s += v; mx = fmaxf(mx, v);
        }
        mms[j] = s * (1.f / C2N);
        mxs[j] = mx;
    }
    __syncthreads();

    {
        float ssa = sag[0] * rsqrtf(sav[0] + EPSF);
        float sha = sab[0] - sam[0] * ssa;
        for (int j = tid; j < tw; j += 256) {
            int t = t0 + j;
            float acc = 0.f;
            #pragma unroll
            for (int kw = 0; kw < 3; ++kw) {
                int tt = t - 1 + kw;
                if (tt >= 0 && tt < TTOT)
                    acc += saw[3 + kw] * mms[j + kw] + saw[12 + kw] * mxs[j + kw];
            }
            sgs[j] = sigmf(acc * ssa + sha);
        }
    }
    __syncthreads();

    {
        int c2 = tid & 31, w = tid >> 5;
        if (w < nw) {
            float acc = 0.f;
            #pragma unroll
            for (int j = 0; j < PWN; ++j) {
                int tl = w * PWN + j;
                acc += eluf(h2s[c2 * H2S_S + tl + 1] * sgs[tl]);
            }
            g_q[(b * C2N + c2) * NPOOL + tile * K2B_W + w] = acc * (1.f / PWN);
        }
    }
}

// ============================================================
// Kernel 2c: depthwise sep conv + BN3 + ELU + pool16 -> out
// grid (BB), 256 threads — lane-group-of-16 parallel reduction
// ============================================================
__global__ void __launch_bounds__(256, 4)
k2c_tail(const float* __restrict__ sepw, const float* __restrict__ sepb,
         const float* __restrict__ g3, const float* __restrict__ bb3,
         const float* __restrict__ m3, const float* __restrict__ v3,
         float* __restrict__ out)
{
    __shared__ float qs[C2N * NPOOL];
    __shared__ float sw[C2N * PWN];
    const int b = blockIdx.x, tid = threadIdx.x;
    for (int i = tid; i < C2N * NPOOL; i += 256)
        qs[i] = g_q[b * C2N * NPOOL + i];
    for (int i = tid; i < C2N * PWN; i += 256)
        sw[i] = sepw[i];
    __syncthreads();

    const int j  = tid & 15;
    const int e0 = tid >> 4;
    for (int r = 0; r < 6; ++r) {
        int e  = e0 + r * 16;          // 0..95 = c2*3 + to
        int c2 = e / 3, to = e % 3;
        int t  = to * PWN + j;
        float y = sepb[c2];
        #pragma unroll
        for (int u = 0; u < PWN; ++u) {
            int tq = t - 7 + u;
            if (tq >= 0 && tq < NPOOL) y = fmaf(sw[c2 * PWN + u], qs[c2 * NPOOL + tq], y);
        }
        float s3  = g3[c2] * rsqrtf(v3[c2] + EPSF);
        float sh3 = bb3[c2] - m3[c2] * s3;
        float v = eluf(y * s3 + sh3);
        #pragma unroll
        for (int o = 8; o > 0; o >>= 1)
            v += __shfl_down_sync(0xffffffffu, v, o, 16);
        if (j == 0) out[b * (C2N * 3) + e] = v * (1.f / PWN);
    }
}

// ============================================================
extern "C" void kernel_launch(void* const* d_in, const int* in_sizes, int n_in,
                              void* d_out, int out_size)
{
    const float* x     = (const float*)d_in[0];
    const float* ahat  = (const float*)d_in[1];
    const float* w1    = (const float*)d_in[2];
    const float* b1c   = (const float*)d_in[3];
    const float* g1    = (const float*)d_in[4];
    const float* bb1   = (const float*)d_in[5];
    const float* m1    = (const float*)d_in[6];
    const float* v1    = (const float*)d_in[7];
    const float* gcw   = (const float*)d_in[8];
    const float* gcb   = (const float*)d_in[9];
    const float* dww   = (const float*)d_in[10];
    const float* dwb   = (const float*)d_in[11];
    const float* g2    = (const float*)d_in[12];
    const float* bb2   = (const float*)d_in[13];
    const float* m2    = (const float*)d_in[14];
    const float* v2    = (const float*)d_in[15];
    const float* caw1  = (const float*)d_in[16];
    const float* cab1  = (const float*)d_in[17];
    const float* caw2  = (const float*)d_in[18];
    const float* cab2  = (const float*)d_in[19];
    const float* saw   = (const float*)d_in[20];
    const float* sag   = (const float*)d_in[21];
    const float* sab   = (const float*)d_in[22];
    const float* sam   = (const float*)d_in[23];
    const float* sav   = (const float*)d_in[24];
    const float* sepw  = (const float*)d_in[25];
    const float* sepb  = (const float*)d_in[26];
    const float* g3    = (const float*)d_in[27];
    const float* bb3   = (const float*)d_in[28];
    const float* m3    = (const float*)d_in[29];
    const float* v3    = (const float*)d_in[30];

    cudaFuncSetAttribute(k1_front, cudaFuncAttributeMaxDynamicSharedMemorySize,
                         SMEM_BYTES);

    dim3 grid1(NTILE, BB);
    k1_front<<<grid1, 1024, SMEM_BYTES>>>(x, ahat, w1, b1c, g1, bb1, m1, v1,
                                          gcw, gcb, dww, dwb, g2, bb2, m2, v2);

    dim3 grid2b(NTILE2, BB);
    k2b_attpool<<<grid2b, 256>>>(caw1, cab1, caw2, cab2, saw, sag, sab, sam, sav);

    k2c_tail<<<BB, 256>>>(sepw, sepb, g3, bb3, m3, v3, (float*)d_out);
}